// round 12
// baseline (speedup 1.0000x reference)
#include <cuda_runtime.h>
#include <cuda_fp16.h>
#include <cstdint>

#define N_USER 100000
#define N_ITEM 200000
#define N_NODE 300000
#define LATDIM 64
#define E_INTER 4000000
#define E_SOC   2000000
#define E_TOT   (E_INTER + E_SOC)
#define N_LAYER 4
#define NBINS   (N_NODE + N_USER)   // inter bins [0,300000), soc bins [300000,400000)

#define NUF ((size_t)N_USER * LATDIM)
#define NNF ((size_t)N_NODE * LATDIM)

// fp16 embeddings: fused16[0]=fp16(concat(uE,iE)); fused16[1..4] gated outputs;
// soc16[1..3] raw soc accumulations (soc16[4] never materialized — its only
// consumer, gate4, runs register-resident in the SpMM epilogue).
__device__ __half g_fused16[5][NNF];
__device__ __half g_soc16[3][NUF];
// CSR: edges sorted by destination bin. rec = {col, val_f32_bits}.
__device__ uint2 g_csr[E_TOT];
__device__ int   g_P[NBINS];        // counts -> exclusive prefix -> bin ends
__device__ int   g_bsum[256];

// ---------------------------------------------------------------------------
// Stage 1: zero bin counters.
// ---------------------------------------------------------------------------
__global__ __launch_bounds__(256) void zerobins_kernel(int* __restrict__ P) {
    int i = blockIdx.x * 256 + threadIdx.x;
    if (i < NBINS) P[i] = 0;
}

// ---------------------------------------------------------------------------
// Stage 2: histogram of destination bins (+ build fused16[0], independent).
// ---------------------------------------------------------------------------
#define H_I 15625            // E_INTER / 256
#define H_S 7813             // ceil(E_SOC / 256)
#define H_B 1024             // fused16[0] build

__global__ __launch_bounds__(256) void hist_kernel(
    int* __restrict__ P,
    const int* __restrict__ ir, const int* __restrict__ sr,
    const float4* __restrict__ uE4, const float4* __restrict__ iE4,
    uint2* __restrict__ h0)
{
    unsigned b = blockIdx.x;
    int tid = threadIdx.x;
    if (b < H_I) {
        int e = (int)b * 256 + tid;
        atomicAdd(P + __ldg(ir + e), 1);
    } else if (b < H_I + H_S) {
        int e = (int)(b - H_I) * 256 + tid;
        if (e < E_SOC) atomicAdd(P + N_NODE + __ldg(sr + e), 1);
    } else {
        const size_t nU4 = NUF / 4, nN4 = NNF / 4;
        size_t stride = (size_t)H_B * 256;
        for (size_t i = (size_t)(b - H_I - H_S) * 256 + tid; i < nN4; i += stride) {
            float4 v = (i < nU4) ? __ldg(uE4 + i) : __ldg(iE4 + (i - nU4));
            __half2 a = __floats2half2_rn(v.x, v.y);
            __half2 c = __floats2half2_rn(v.z, v.w);
            uint2 st;
            st.x = *reinterpret_cast<unsigned*>(&a);
            st.y = *reinterpret_cast<unsigned*>(&c);
            h0[i] = st;
        }
    }
}

// ---------------------------------------------------------------------------
// Stage 3: per-block scan. Stage 4: addoff (re-derives the 196-entry top
// scan in shared per block).
// ---------------------------------------------------------------------------
#define SCAN_ELEMS 2048
#define SCAN_BLOCKS ((NBINS + SCAN_ELEMS - 1) / SCAN_ELEMS)   // 196

__global__ __launch_bounds__(256) void scan_blocks_kernel(
    int* __restrict__ P, int* __restrict__ bsum)
{
    __shared__ int sh[256];
    int b = blockIdx.x, t = threadIdx.x;
    int base = b * SCAN_ELEMS + t * 8;
    int v[8], s = 0;
    #pragma unroll
    for (int i = 0; i < 8; i++) {
        v[i] = (base + i < NBINS) ? P[base + i] : 0;
        s += v[i];
    }
    sh[t] = s;
    __syncthreads();
    #pragma unroll
    for (int off = 1; off < 256; off <<= 1) {
        int x = sh[t];
        int y = (t >= off) ? sh[t - off] : 0;
        __syncthreads();
        sh[t] = x + y;
        __syncthreads();
    }
    int run = sh[t] - s;
    #pragma unroll
    for (int i = 0; i < 8; i++) {
        int nv = run;
        run += v[i];
        if (base + i < NBINS) P[base + i] = nv;
    }
    if (t == 255) bsum[b] = run;
}

__global__ __launch_bounds__(256) void addoff_kernel(
    int* __restrict__ P, const int* __restrict__ bsum)
{
    __shared__ int sh[256];
    int t = threadIdx.x;
    int v = (t < SCAN_BLOCKS) ? __ldg(bsum + t) : 0;
    sh[t] = v;
    __syncthreads();
    #pragma unroll
    for (int off = 1; off < 256; off <<= 1) {
        int x = sh[t];
        int y = (t >= off) ? sh[t - off] : 0;
        __syncthreads();
        sh[t] = x + y;
        __syncthreads();
    }
    sh[t] = sh[t] - v;   // exclusive
    __syncthreads();
    int i = blockIdx.x * 256 + t;
    if (i < NBINS) P[i] += sh[i / SCAN_ELEMS];
}

// ---------------------------------------------------------------------------
// Stage 5: scatter edges into CSR slots (fetch-add turns P into bin ends).
// ---------------------------------------------------------------------------
__global__ __launch_bounds__(256) void scatter_kernel(
    int* __restrict__ P, uint2* __restrict__ csr,
    const int* __restrict__ ir, const int* __restrict__ ic, const float* __restrict__ iv,
    const int* __restrict__ sr, const int* __restrict__ sc, const float* __restrict__ sv)
{
    unsigned b = blockIdx.x;
    int tid = threadIdx.x;
    uint2 rec;
    int bin;
    if (b < H_I) {
        int e = (int)b * 256 + tid;
        bin = __ldg(ir + e);
        rec.x = (unsigned)__ldg(ic + e);
        rec.y = __float_as_uint(__ldg(iv + e));
    } else {
        int e = (int)(b - H_I) * 256 + tid;
        if (e >= E_SOC) return;
        bin = N_NODE + __ldg(sr + e);
        rec.x = (unsigned)__ldg(sc + e);
        rec.y = __float_as_uint(__ldg(sv + e));
    }
    int slot = atomicAdd(P + bin, 1);
    csr[slot] = rec;
}

// ---------------------------------------------------------------------------
// Edge-chunk processors: 4-edge and 1-edge steps for a 16-lane group.
// Lane owns 4 halves (uint2 = 8 B); gather = 128 B/edge = 1 L1 wavefront;
// f32 register accumulation.
// ---------------------------------------------------------------------------
__device__ __forceinline__ void proc4(
    uint2 rec, int j, unsigned mask,
    const __half* __restrict__ X, int lane, float4& acc)
{
    int c0 = __shfl_sync(mask, (int)rec.x, j, 16);
    int c1 = __shfl_sync(mask, (int)rec.x, j + 1, 16);
    int c2 = __shfl_sync(mask, (int)rec.x, j + 2, 16);
    int c3 = __shfl_sync(mask, (int)rec.x, j + 3, 16);
    float v0 = __uint_as_float(__shfl_sync(mask, rec.y, j, 16));
    float v1 = __uint_as_float(__shfl_sync(mask, rec.y, j + 1, 16));
    float v2 = __uint_as_float(__shfl_sync(mask, rec.y, j + 2, 16));
    float v3 = __uint_as_float(__shfl_sync(mask, rec.y, j + 3, 16));
    uint2 h0 = __ldg(reinterpret_cast<const uint2*>(X + (size_t)c0 * LATDIM) + lane);
    uint2 h1 = __ldg(reinterpret_cast<const uint2*>(X + (size_t)c1 * LATDIM) + lane);
    uint2 h2 = __ldg(reinterpret_cast<const uint2*>(X + (size_t)c2 * LATDIM) + lane);
    uint2 h3 = __ldg(reinterpret_cast<const uint2*>(X + (size_t)c3 * LATDIM) + lane);
    float2 a0 = __half22float2(*reinterpret_cast<__half2*>(&h0.x));
    float2 b0 = __half22float2(*reinterpret_cast<__half2*>(&h0.y));
    float2 a1 = __half22float2(*reinterpret_cast<__half2*>(&h1.x));
    float2 b1 = __half22float2(*reinterpret_cast<__half2*>(&h1.y));
    float2 a2 = __half22float2(*reinterpret_cast<__half2*>(&h2.x));
    float2 b2 = __half22float2(*reinterpret_cast<__half2*>(&h2.y));
    float2 a3 = __half22float2(*reinterpret_cast<__half2*>(&h3.x));
    float2 b3 = __half22float2(*reinterpret_cast<__half2*>(&h3.y));
    acc.x = fmaf(v0, a0.x, acc.x); acc.y = fmaf(v0, a0.y, acc.y);
    acc.z = fmaf(v0, b0.x, acc.z); acc.w = fmaf(v0, b0.y, acc.w);
    acc.x = fmaf(v1, a1.x, acc.x); acc.y = fmaf(v1, a1.y, acc.y);
    acc.z = fmaf(v1, b1.x, acc.z); acc.w = fmaf(v1, b1.y, acc.w);
    acc.x = fmaf(v2, a2.x, acc.x); acc.y = fmaf(v2, a2.y, acc.y);
    acc.z = fmaf(v2, b2.x, acc.z); acc.w = fmaf(v2, b2.y, acc.w);
    acc.x = fmaf(v3, a3.x, acc.x); acc.y = fmaf(v3, a3.y, acc.y);
    acc.z = fmaf(v3, b3.x, acc.z); acc.w = fmaf(v3, b3.y, acc.w);
}

__device__ __forceinline__ void proc1(
    uint2 rec, int j, unsigned mask,
    const __half* __restrict__ X, int lane, float4& acc)
{
    int c = __shfl_sync(mask, (int)rec.x, j, 16);
    float v = __uint_as_float(__shfl_sync(mask, rec.y, j, 16));
    uint2 h = __ldg(reinterpret_cast<const uint2*>(X + (size_t)c * LATDIM) + lane);
    float2 a = __half22float2(*reinterpret_cast<__half2*>(&h.x));
    float2 b = __half22float2(*reinterpret_cast<__half2*>(&h.y));
    acc.x = fmaf(v, a.x, acc.x); acc.y = fmaf(v, a.y, acc.y);
    acc.z = fmaf(v, b.x, acc.z); acc.w = fmaf(v, b.y, acc.w);
}

__device__ __forceinline__ void store_h4(__half* O, size_t row, int lane, float4 v) {
    __half2 lo = __floats2half2_rn(v.x, v.y);
    __half2 hi = __floats2half2_rn(v.z, v.w);
    uint2 st;
    st.x = *reinterpret_cast<unsigned*>(&lo);
    st.y = *reinterpret_cast<unsigned*>(&hi);
    *(reinterpret_cast<uint2*>(O + row * LATDIM) + lane) = st;
}

// ---------------------------------------------------------------------------
// Fused SpMM + gate: 16-lane group per node row. User rows run inter+soc
// accumulation INTERLEAVED (both CSR batches streamed via __ldcs, 4-edge
// chunks alternated → 8 gathers in flight), then apply the gate in registers
// and store gated fused16 + raw soc16. Item rows: inter accumulation only.
// ---------------------------------------------------------------------------
__global__ __launch_bounds__(256) void spmm_gate_kernel(
    const uint2* __restrict__ csr, const int* __restrict__ P,
    const __half* __restrict__ xI,   // fused16[k] (all nodes)
    const __half* __restrict__ xS,   // soc source layer k (user rows)
    __half* __restrict__ oF,         // fused16[k+1]
    __half* __restrict__ oS,         // soc16[k+1] or null (last layer)
    const float* __restrict__ Wg,    // (2,128) gate k+1
    const float* __restrict__ bg)    // (2,)
{
    int t = blockIdx.x * 256 + threadIdx.x;
    int row = t >> 4;
    int lane = t & 15;
    if (row >= N_NODE) return;
    unsigned mask = 0xFFFFu << (threadIdx.x & 16);

    if (row < N_USER) {
        int sI = (row == 0) ? 0 : __ldg(P + row - 1);
        int eI = __ldg(P + row);
        int sS = __ldg(P + N_NODE + row - 1);
        int eS = __ldg(P + N_NODE + row);

        float4 accI = make_float4(0.f, 0.f, 0.f, 0.f);
        float4 accS = make_float4(0.f, 0.f, 0.f, 0.f);
        int e0I = sI, e0S = sS;
        while (e0I < eI || e0S < eS) {
            uint2 recI = (e0I + lane < eI) ? __ldcs(csr + e0I + lane) : make_uint2(0u, 0u);
            uint2 recS = (e0S + lane < eS) ? __ldcs(csr + e0S + lane) : make_uint2(0u, 0u);
            int nbI = min(16, max(0, eI - e0I));
            int nbS = min(16, max(0, eS - e0S));
            int jI = 0, jS = 0;
            // interleaved 4-edge chunks: 8 gathers in flight
            while (jI + 4 <= nbI && jS + 4 <= nbS) {
                proc4(recI, jI, mask, xI, lane, accI);
                proc4(recS, jS, mask, xS, lane, accS);
                jI += 4; jS += 4;
            }
            for (; jI + 4 <= nbI; jI += 4) proc4(recI, jI, mask, xI, lane, accI);
            for (; jS + 4 <= nbS; jS += 4) proc4(recS, jS, mask, xS, lane, accS);
            for (; jI < nbI; jI++) proc1(recI, jI, mask, xI, lane, accI);
            for (; jS < nbS; jS++) proc1(recS, jS, mask, xS, lane, accS);
            e0I += 16; e0S += 16;
        }

        // gate: a_j = [accS, accI] . Wg[j], reduce over 16 lanes
        int d = lane * 4;
        float a0 = accS.x * __ldg(Wg + d)        + accS.y * __ldg(Wg + d + 1)
                 + accS.z * __ldg(Wg + d + 2)    + accS.w * __ldg(Wg + d + 3)
                 + accI.x * __ldg(Wg + 64 + d)   + accI.y * __ldg(Wg + 64 + d + 1)
                 + accI.z * __ldg(Wg + 64 + d + 2) + accI.w * __ldg(Wg + 64 + d + 3);
        float a1 = accS.x * __ldg(Wg + 128 + d)  + accS.y * __ldg(Wg + 128 + d + 1)
                 + accS.z * __ldg(Wg + 128 + d + 2) + accS.w * __ldg(Wg + 128 + d + 3)
                 + accI.x * __ldg(Wg + 192 + d)  + accI.y * __ldg(Wg + 192 + d + 1)
                 + accI.z * __ldg(Wg + 192 + d + 2) + accI.w * __ldg(Wg + 192 + d + 3);
        #pragma unroll
        for (int o = 8; o; o >>= 1) {
            a0 += __shfl_xor_sync(mask, a0, o, 16);
            a1 += __shfl_xor_sync(mask, a1, o, 16);
        }
        a0 += __ldg(bg);
        a1 += __ldg(bg + 1);
        a0 = a0 > 0.f ? a0 : 0.01f * a0;
        a1 = a1 > 0.f ? a1 : 0.01f * a1;
        float mx = fmaxf(a0, a1);
        float e0 = __expf(a0 - mx), e1 = __expf(a1 - mx);
        float inv = 1.f / (e0 + e1);
        float m0 = e0 * inv, m1 = e1 * inv;
        float4 g;
        g.x = accS.x * m0 + accI.x * m1;
        g.y = accS.y * m0 + accI.y * m1;
        g.z = accS.z * m0 + accI.z * m1;
        g.w = accS.w * m0 + accI.w * m1;
        store_h4(oF, (size_t)row, lane, g);
        if (oS) store_h4(oS, (size_t)row, lane, accS);
    } else {
        int start = __ldg(P + row - 1);   // row >= N_USER >= 1
        int end = __ldg(P + row);
        float4 acc = make_float4(0.f, 0.f, 0.f, 0.f);
        for (int e0 = start; e0 < end; e0 += 16) {
            uint2 rec = (e0 + lane < end) ? __ldcs(csr + e0 + lane) : make_uint2(0u, 0u);
            int nb = min(16, end - e0);
            int j = 0;
            for (; j + 4 <= nb; j += 4) proc4(rec, j, mask, xI, lane, acc);
            for (; j < nb; j++) proc1(rec, j, mask, xI, lane, acc);
        }
        store_h4(oF, (size_t)row, lane, acc);
    }
}

// ---------------------------------------------------------------------------
// Final combine: one warp per node; layer-0 rows from uE/iE (f32).
// ---------------------------------------------------------------------------
__global__ __launch_bounds__(256) void final_kernel(
    const float* __restrict__ uE, const float* __restrict__ iE,
    const __half* __restrict__ F1, const __half* __restrict__ F2,
    const __half* __restrict__ F3, const __half* __restrict__ F4,
    const float* __restrict__ WL1, const float* __restrict__ bL1,
    const float* __restrict__ WL2, const float* __restrict__ bL2,
    float* __restrict__ out)
{
    int w = (blockIdx.x * blockDim.x + threadIdx.x) >> 5;
    int lane = threadIdx.x & 31;
    if (w >= N_NODE) return;
    bool isU = (w < N_USER);
    const float* W = isU ? WL1 : WL2;
    const float* b = isU ? bL1 : bL2;
    size_t base = (size_t)w * LATDIM + lane * 2;
    float2 f[5];
    f[0] = isU ? *reinterpret_cast<const float2*>(uE + base)
               : *reinterpret_cast<const float2*>(iE + (base - NUF));
    f[1] = __half22float2(*reinterpret_cast<const __half2*>(F1 + base));
    f[2] = __half22float2(*reinterpret_cast<const __half2*>(F2 + base));
    f[3] = __half22float2(*reinterpret_cast<const __half2*>(F3 + base));
    f[4] = __half22float2(*reinterpret_cast<const __half2*>(F4 + base));
    float lg[5];
    int d = lane * 2;
    #pragma unroll
    for (int j = 0; j < 5; j++) {
        float acc = 0.f;
        #pragma unroll
        for (int k = 0; k < 5; k++) {
            const float* wr = W + j * 320 + k * 64 + d;
            acc += f[k].x * __ldg(wr) + f[k].y * __ldg(wr + 1);
        }
        lg[j] = acc;
    }
    #pragma unroll
    for (int o = 16; o; o >>= 1) {
        #pragma unroll
        for (int j = 0; j < 5; j++) lg[j] += __shfl_xor_sync(0xffffffffu, lg[j], o);
    }
    float mx = -1e30f;
    #pragma unroll
    for (int j = 0; j < 5; j++) {
        lg[j] += __ldg(b + j);
        lg[j] = lg[j] > 0.f ? lg[j] : 0.01f * lg[j];
        mx = fmaxf(mx, lg[j]);
    }
    float s = 0.f;
    #pragma unroll
    for (int j = 0; j < 5; j++) { lg[j] = __expf(lg[j] - mx); s += lg[j]; }
    float inv = 1.f / s;
    float2 o2 = make_float2(0.f, 0.f);
    #pragma unroll
    for (int j = 0; j < 5; j++) {
        float wk = lg[j] * inv;
        o2.x += wk * f[j].x;
        o2.y += wk * f[j].y;
    }
    *reinterpret_cast<float2*>(out + base) = o2;
}

// ---------------------------------------------------------------------------
// host
// ---------------------------------------------------------------------------
static inline int cdiv_ll(long long a, int b) { return (int)((a + b - 1) / b); }

extern "C" void kernel_launch(void* const* d_in, const int* in_sizes, int n_in,
                              void* d_out, int out_size)
{
    const float* uE  = (const float*)d_in[0];
    const float* iE  = (const float*)d_in[1];
    const float* Wg  = (const float*)d_in[2];
    const float* bg  = (const float*)d_in[3];
    const float* WL1 = (const float*)d_in[4];
    const float* bL1 = (const float*)d_in[5];
    const float* WL2 = (const float*)d_in[6];
    const float* bL2 = (const float*)d_in[7];
    const int*   ir  = (const int*)d_in[8];
    const int*   ic  = (const int*)d_in[9];
    const float* iv  = (const float*)d_in[10];
    const int*   sr  = (const int*)d_in[11];
    const int*   sc  = (const int*)d_in[12];
    const float* sv  = (const float*)d_in[13];
    float* out = (float*)d_out;

    void *pf16, *ps16, *pcsr, *pP, *pbs;
    cudaGetSymbolAddress(&pf16, g_fused16);
    cudaGetSymbolAddress(&ps16, g_soc16);
    cudaGetSymbolAddress(&pcsr, g_csr);
    cudaGetSymbolAddress(&pP, g_P);
    cudaGetSymbolAddress(&pbs, g_bsum);

    __half* fused16[5];
    for (int k = 0; k <= 4; k++) fused16[k] = (__half*)pf16 + (size_t)k * NNF;
    __half* soc16[4];   // soc16[1..3]
    for (int l = 1; l <= 3; l++) soc16[l] = (__half*)ps16 + (size_t)(l - 1) * NUF;
    __half* socsrc[4];
    socsrc[0] = fused16[0];   // layer-0 soc source = fused16[0] user rows
    for (int l = 1; l < 4; l++) socsrc[l] = soc16[l];
    uint2* csr = (uint2*)pcsr;
    int* P = (int*)pP;
    int* bsum = (int*)pbs;

    // --- CSR build + fused16[0] ---
    zerobins_kernel<<<cdiv_ll(NBINS, 256), 256>>>(P);
    hist_kernel<<<H_I + H_S + H_B, 256>>>(
        P, ir, sr, (const float4*)uE, (const float4*)iE, (uint2*)fused16[0]);
    scan_blocks_kernel<<<SCAN_BLOCKS, 256>>>(P, bsum);
    addoff_kernel<<<cdiv_ll(NBINS, 256), 256>>>(P, bsum);
    scatter_kernel<<<H_I + H_S, 256>>>(P, csr, ir, ic, iv, sr, sc, sv);

    // --- fused SpMM + gate layers ---
    const int SPMM_BLOCKS = cdiv_ll((long long)N_NODE * 16, 256);  // 18750
    for (int k = 0; k < N_LAYER; k++) {
        spmm_gate_kernel<<<SPMM_BLOCKS, 256>>>(
            csr, P,
            fused16[k], socsrc[k],
            fused16[k + 1],
            (k < 3) ? soc16[k + 1] : (__half*)nullptr,
            Wg + (size_t)(k + 1) * 256, bg + (size_t)(k + 1) * 2);
    }

    final_kernel<<<cdiv_ll((long long)N_NODE * 32, 256), 256>>>(
        uE, iE, fused16[1], fused16[2], fused16[3], fused16[4],
        WL1, bL1, WL2, bL2, out);
}

// round 15
// speedup vs baseline: 1.1849x; 1.1849x over previous
#include <cuda_runtime.h>
#include <cuda_fp16.h>
#include <cstdint>

#define N_USER 100000
#define N_ITEM 200000
#define N_NODE 300000
#define LATDIM 64
#define E_INTER 4000000
#define E_SOC   2000000
#define E_TOT   (E_INTER + E_SOC)
#define N_LAYER 4
#define NBINS   (N_NODE + N_USER)   // inter bins [0,300000), soc bins [300000,400000)

#define NUF ((size_t)N_USER * LATDIM)
#define NNF ((size_t)N_NODE * LATDIM)

// fp16 embeddings: fused16[0]=fp16(concat(uE,iE)); fused16[1..4] gated outputs;
// soc16[1..3] raw soc accumulations (soc16[4] never materialized — its only
// consumer, gate4, runs register-resident in the SpMM epilogue).
__device__ __half g_fused16[5][NNF];
__device__ __half g_soc16[3][NUF];
// CSR: edges sorted by destination bin. rec = {col, val_f32_bits}.
__device__ uint2 g_csr[E_TOT];
__device__ int   g_P[NBINS];        // counts -> exclusive prefix -> bin ends
__device__ int   g_bsum[256];

// ---------------------------------------------------------------------------
// Stage 1: zero bin counters.
// ---------------------------------------------------------------------------
__global__ __launch_bounds__(256) void zerobins_kernel(int* __restrict__ P) {
    int i = blockIdx.x * 256 + threadIdx.x;
    if (i < NBINS) P[i] = 0;
}

// ---------------------------------------------------------------------------
// Stage 2: histogram of destination bins (+ build fused16[0], independent).
// ---------------------------------------------------------------------------
#define H_I 15625            // E_INTER / 256
#define H_S 7813             // ceil(E_SOC / 256)
#define H_B 1024             // fused16[0] build

__global__ __launch_bounds__(256) void hist_kernel(
    int* __restrict__ P,
    const int* __restrict__ ir, const int* __restrict__ sr,
    const float4* __restrict__ uE4, const float4* __restrict__ iE4,
    uint2* __restrict__ h0)
{
    unsigned b = blockIdx.x;
    int tid = threadIdx.x;
    if (b < H_I) {
        int e = (int)b * 256 + tid;
        atomicAdd(P + __ldg(ir + e), 1);
    } else if (b < H_I + H_S) {
        int e = (int)(b - H_I) * 256 + tid;
        if (e < E_SOC) atomicAdd(P + N_NODE + __ldg(sr + e), 1);
    } else {
        const size_t nU4 = NUF / 4, nN4 = NNF / 4;
        size_t stride = (size_t)H_B * 256;
        for (size_t i = (size_t)(b - H_I - H_S) * 256 + tid; i < nN4; i += stride) {
            float4 v = (i < nU4) ? __ldg(uE4 + i) : __ldg(iE4 + (i - nU4));
            __half2 a = __floats2half2_rn(v.x, v.y);
            __half2 c = __floats2half2_rn(v.z, v.w);
            uint2 st;
            st.x = *reinterpret_cast<unsigned*>(&a);
            st.y = *reinterpret_cast<unsigned*>(&c);
            h0[i] = st;
        }
    }
}

// ---------------------------------------------------------------------------
// Stage 3: per-block scan. Stage 4: addoff (re-derives the 196-entry top
// scan in shared per block).
// ---------------------------------------------------------------------------
#define SCAN_ELEMS 2048
#define SCAN_BLOCKS ((NBINS + SCAN_ELEMS - 1) / SCAN_ELEMS)   // 196

__global__ __launch_bounds__(256) void scan_blocks_kernel(
    int* __restrict__ P, int* __restrict__ bsum)
{
    __shared__ int sh[256];
    int b = blockIdx.x, t = threadIdx.x;
    int base = b * SCAN_ELEMS + t * 8;
    int v[8], s = 0;
    #pragma unroll
    for (int i = 0; i < 8; i++) {
        v[i] = (base + i < NBINS) ? P[base + i] : 0;
        s += v[i];
    }
    sh[t] = s;
    __syncthreads();
    #pragma unroll
    for (int off = 1; off < 256; off <<= 1) {
        int x = sh[t];
        int y = (t >= off) ? sh[t - off] : 0;
        __syncthreads();
        sh[t] = x + y;
        __syncthreads();
    }
    int run = sh[t] - s;
    #pragma unroll
    for (int i = 0; i < 8; i++) {
        int nv = run;
        run += v[i];
        if (base + i < NBINS) P[base + i] = nv;
    }
    if (t == 255) bsum[b] = run;
}

__global__ __launch_bounds__(256) void addoff_kernel(
    int* __restrict__ P, const int* __restrict__ bsum)
{
    __shared__ int sh[256];
    int t = threadIdx.x;
    int v = (t < SCAN_BLOCKS) ? __ldg(bsum + t) : 0;
    sh[t] = v;
    __syncthreads();
    #pragma unroll
    for (int off = 1; off < 256; off <<= 1) {
        int x = sh[t];
        int y = (t >= off) ? sh[t - off] : 0;
        __syncthreads();
        sh[t] = x + y;
        __syncthreads();
    }
    sh[t] = sh[t] - v;   // exclusive
    __syncthreads();
    int i = blockIdx.x * 256 + t;
    if (i < NBINS) P[i] += sh[i / SCAN_ELEMS];
}

// ---------------------------------------------------------------------------
// Stage 5: scatter edges into CSR slots (fetch-add turns P into bin ends).
// ---------------------------------------------------------------------------
__global__ __launch_bounds__(256) void scatter_kernel(
    int* __restrict__ P, uint2* __restrict__ csr,
    const int* __restrict__ ir, const int* __restrict__ ic, const float* __restrict__ iv,
    const int* __restrict__ sr, const int* __restrict__ sc, const float* __restrict__ sv)
{
    unsigned b = blockIdx.x;
    int tid = threadIdx.x;
    uint2 rec;
    int bin;
    if (b < H_I) {
        int e = (int)b * 256 + tid;
        bin = __ldg(ir + e);
        rec.x = (unsigned)__ldg(ic + e);
        rec.y = __float_as_uint(__ldg(iv + e));
    } else {
        int e = (int)(b - H_I) * 256 + tid;
        if (e >= E_SOC) return;
        bin = N_NODE + __ldg(sr + e);
        rec.x = (unsigned)__ldg(sc + e);
        rec.y = __float_as_uint(__ldg(sv + e));
    }
    int slot = atomicAdd(P + bin, 1);
    csr[slot] = rec;
}

// ---------------------------------------------------------------------------
// Row accumulation: 16-lane group, lane owns 4 halves (uint2 = 8 B);
// gather = 128 B/edge = 1 L1 wavefront; f32 register accumulation.
// CSR metadata loads use __ldcs (streaming, evict-first) so the gather
// source keeps L2 residency. Bounds are passed in (hoisted by caller).
// ---------------------------------------------------------------------------
__device__ __forceinline__ float4 row_accum(
    const uint2* __restrict__ csr, int start, int end,
    const __half* __restrict__ X, int lane, unsigned mask)
{
    float4 acc = make_float4(0.f, 0.f, 0.f, 0.f);
    for (int e0 = start; e0 < end; e0 += 16) {
        uint2 rec = (e0 + lane < end) ? __ldcs(csr + e0 + lane) : make_uint2(0u, 0u);
        int nb = min(16, end - e0);
        int j = 0;
        for (; j + 4 <= nb; j += 4) {
            int c0 = __shfl_sync(mask, (int)rec.x, j, 16);
            int c1 = __shfl_sync(mask, (int)rec.x, j + 1, 16);
            int c2 = __shfl_sync(mask, (int)rec.x, j + 2, 16);
            int c3 = __shfl_sync(mask, (int)rec.x, j + 3, 16);
            float v0 = __uint_as_float(__shfl_sync(mask, rec.y, j, 16));
            float v1 = __uint_as_float(__shfl_sync(mask, rec.y, j + 1, 16));
            float v2 = __uint_as_float(__shfl_sync(mask, rec.y, j + 2, 16));
            float v3 = __uint_as_float(__shfl_sync(mask, rec.y, j + 3, 16));
            uint2 h0 = __ldg(reinterpret_cast<const uint2*>(X + (size_t)c0 * LATDIM) + lane);
            uint2 h1 = __ldg(reinterpret_cast<const uint2*>(X + (size_t)c1 * LATDIM) + lane);
            uint2 h2 = __ldg(reinterpret_cast<const uint2*>(X + (size_t)c2 * LATDIM) + lane);
            uint2 h3 = __ldg(reinterpret_cast<const uint2*>(X + (size_t)c3 * LATDIM) + lane);
            float2 a0 = __half22float2(*reinterpret_cast<__half2*>(&h0.x));
            float2 b0 = __half22float2(*reinterpret_cast<__half2*>(&h0.y));
            float2 a1 = __half22float2(*reinterpret_cast<__half2*>(&h1.x));
            float2 b1 = __half22float2(*reinterpret_cast<__half2*>(&h1.y));
            float2 a2 = __half22float2(*reinterpret_cast<__half2*>(&h2.x));
            float2 b2 = __half22float2(*reinterpret_cast<__half2*>(&h2.y));
            float2 a3 = __half22float2(*reinterpret_cast<__half2*>(&h3.x));
            float2 b3 = __half22float2(*reinterpret_cast<__half2*>(&h3.y));
            acc.x = fmaf(v0, a0.x, acc.x); acc.y = fmaf(v0, a0.y, acc.y);
            acc.z = fmaf(v0, b0.x, acc.z); acc.w = fmaf(v0, b0.y, acc.w);
            acc.x = fmaf(v1, a1.x, acc.x); acc.y = fmaf(v1, a1.y, acc.y);
            acc.z = fmaf(v1, b1.x, acc.z); acc.w = fmaf(v1, b1.y, acc.w);
            acc.x = fmaf(v2, a2.x, acc.x); acc.y = fmaf(v2, a2.y, acc.y);
            acc.z = fmaf(v2, b2.x, acc.z); acc.w = fmaf(v2, b2.y, acc.w);
            acc.x = fmaf(v3, a3.x, acc.x); acc.y = fmaf(v3, a3.y, acc.y);
            acc.z = fmaf(v3, b3.x, acc.z); acc.w = fmaf(v3, b3.y, acc.w);
        }
        for (; j < nb; j++) {
            int c = __shfl_sync(mask, (int)rec.x, j, 16);
            float v = __uint_as_float(__shfl_sync(mask, rec.y, j, 16));
            uint2 h = __ldg(reinterpret_cast<const uint2*>(X + (size_t)c * LATDIM) + lane);
            float2 a = __half22float2(*reinterpret_cast<__half2*>(&h.x));
            float2 bb = __half22float2(*reinterpret_cast<__half2*>(&h.y));
            acc.x = fmaf(v, a.x, acc.x); acc.y = fmaf(v, a.y, acc.y);
            acc.z = fmaf(v, bb.x, acc.z); acc.w = fmaf(v, bb.y, acc.w);
        }
    }
    return acc;
}

__device__ __forceinline__ void store_h4(__half* O, size_t row, int lane, float4 v) {
    __half2 lo = __floats2half2_rn(v.x, v.y);
    __half2 hi = __floats2half2_rn(v.z, v.w);
    uint2 st;
    st.x = *reinterpret_cast<unsigned*>(&lo);
    st.y = *reinterpret_cast<unsigned*>(&hi);
    *(reinterpret_cast<uint2*>(O + row * LATDIM) + lane) = st;
}

// ---------------------------------------------------------------------------
// Fused SpMM + gate: 16-lane group per node row (R10 structure). User rows
// run inter then soc accumulation (all 4 P pointers hoisted upfront), apply
// the gate in registers, store gated fused16 + raw soc16. Item rows: inter
// accumulation only.
// ---------------------------------------------------------------------------
__global__ __launch_bounds__(256) void spmm_gate_kernel(
    const uint2* __restrict__ csr, const int* __restrict__ P,
    const __half* __restrict__ xI,   // fused16[k] (all nodes)
    const __half* __restrict__ xS,   // soc source layer k (user rows)
    __half* __restrict__ oF,         // fused16[k+1]
    __half* __restrict__ oS,         // soc16[k+1] or null (last layer)
    const float* __restrict__ Wg,    // (2,128) gate k+1
    const float* __restrict__ bg)    // (2,)
{
    int t = blockIdx.x * 256 + threadIdx.x;
    int row = t >> 4;
    int lane = t & 15;
    if (row >= N_NODE) return;
    unsigned mask = 0xFFFFu << (threadIdx.x & 16);

    if (row < N_USER) {
        // hoist all four row pointers before any gather chain
        int sI = (row == 0) ? 0 : __ldg(P + row - 1);
        int eI = __ldg(P + row);
        int sS = __ldg(P + N_NODE + row - 1);
        int eS = __ldg(P + N_NODE + row);

        float4 accI = row_accum(csr, sI, eI, xI, lane, mask);
        float4 accS = row_accum(csr, sS, eS, xS, lane, mask);

        // gate: a_j = [accS, accI] . Wg[j], reduce over 16 lanes
        int d = lane * 4;
        float a0 = accS.x * __ldg(Wg + d)        + accS.y * __ldg(Wg + d + 1)
                 + accS.z * __ldg(Wg + d + 2)    + accS.w * __ldg(Wg + d + 3)
                 + accI.x * __ldg(Wg + 64 + d)   + accI.y * __ldg(Wg + 64 + d + 1)
                 + accI.z * __ldg(Wg + 64 + d + 2) + accI.w * __ldg(Wg + 64 + d + 3);
        float a1 = accS.x * __ldg(Wg + 128 + d)  + accS.y * __ldg(Wg + 128 + d + 1)
                 + accS.z * __ldg(Wg + 128 + d + 2) + accS.w * __ldg(Wg + 128 + d + 3)
                 + accI.x * __ldg(Wg + 192 + d)  + accI.y * __ldg(Wg + 192 + d + 1)
                 + accI.z * __ldg(Wg + 192 + d + 2) + accI.w * __ldg(Wg + 192 + d + 3);
        #pragma unroll
        for (int o = 8; o; o >>= 1) {
            a0 += __shfl_xor_sync(mask, a0, o, 16);
            a1 += __shfl_xor_sync(mask, a1, o, 16);
        }
        a0 += __ldg(bg);
        a1 += __ldg(bg + 1);
        a0 = a0 > 0.f ? a0 : 0.01f * a0;
        a1 = a1 > 0.f ? a1 : 0.01f * a1;
        float mx = fmaxf(a0, a1);
        float e0 = __expf(a0 - mx), e1 = __expf(a1 - mx);
        float inv = 1.f / (e0 + e1);
        float m0 = e0 * inv, m1 = e1 * inv;
        float4 g;
        g.x = accS.x * m0 + accI.x * m1;
        g.y = accS.y * m0 + accI.y * m1;
        g.z = accS.z * m0 + accI.z * m1;
        g.w = accS.w * m0 + accI.w * m1;
        store_h4(oF, (size_t)row, lane, g);
        if (oS) store_h4(oS, (size_t)row, lane, accS);
    } else {
        int start = __ldg(P + row - 1);   // row >= N_USER >= 1
        int end = __ldg(P + row);
        float4 acc = row_accum(csr, start, end, xI, lane, mask);
        store_h4(oF, (size_t)row, lane, acc);
    }
}

// ---------------------------------------------------------------------------
// Final combine: one warp per node, all five layers read as fp16.
// ---------------------------------------------------------------------------
__global__ __launch_bounds__(256) void final_kernel(
    const __half* __restrict__ F0, const __half* __restrict__ F1,
    const __half* __restrict__ F2, const __half* __restrict__ F3,
    const __half* __restrict__ F4,
    const float* __restrict__ WL1, const float* __restrict__ bL1,
    const float* __restrict__ WL2, const float* __restrict__ bL2,
    float* __restrict__ out)
{
    int w = (blockIdx.x * blockDim.x + threadIdx.x) >> 5;
    int lane = threadIdx.x & 31;
    if (w >= N_NODE) return;
    bool isU = (w < N_USER);
    const float* W = isU ? WL1 : WL2;
    const float* b = isU ? bL1 : bL2;
    size_t base = (size_t)w * LATDIM + lane * 2;
    float2 f[5];
    f[0] = __half22float2(*reinterpret_cast<const __half2*>(F0 + base));
    f[1] = __half22float2(*reinterpret_cast<const __half2*>(F1 + base));
    f[2] = __half22float2(*reinterpret_cast<const __half2*>(F2 + base));
    f[3] = __half22float2(*reinterpret_cast<const __half2*>(F3 + base));
    f[4] = __half22float2(*reinterpret_cast<const __half2*>(F4 + base));
    float lg[5];
    int d = lane * 2;
    #pragma unroll
    for (int j = 0; j < 5; j++) {
        float acc = 0.f;
        #pragma unroll
        for (int k = 0; k < 5; k++) {
            const float* wr = W + j * 320 + k * 64 + d;
            acc += f[k].x * __ldg(wr) + f[k].y * __ldg(wr + 1);
        }
        lg[j] = acc;
    }
    #pragma unroll
    for (int o = 16; o; o >>= 1) {
        #pragma unroll
        for (int j = 0; j < 5; j++) lg[j] += __shfl_xor_sync(0xffffffffu, lg[j], o);
    }
    float mx = -1e30f;
    #pragma unroll
    for (int j = 0; j < 5; j++) {
        lg[j] += __ldg(b + j);
        lg[j] = lg[j] > 0.f ? lg[j] : 0.01f * lg[j];
        mx = fmaxf(mx, lg[j]);
    }
    float s = 0.f;
    #pragma unroll
    for (int j = 0; j < 5; j++) { lg[j] = __expf(lg[j] - mx); s += lg[j]; }
    float inv = 1.f / s;
    float2 o2 = make_float2(0.f, 0.f);
    #pragma unroll
    for (int j = 0; j < 5; j++) {
        float wk = lg[j] * inv;
        o2.x += wk * f[j].x;
        o2.y += wk * f[j].y;
    }
    *reinterpret_cast<float2*>(out + base) = o2;
}

// ---------------------------------------------------------------------------
// host
// ---------------------------------------------------------------------------
static inline int cdiv_ll(long long a, int b) { return (int)((a + b - 1) / b); }

extern "C" void kernel_launch(void* const* d_in, const int* in_sizes, int n_in,
                              void* d_out, int out_size)
{
    const float* uE  = (const float*)d_in[0];
    const float* iE  = (const float*)d_in[1];
    const float* Wg  = (const float*)d_in[2];
    const float* bg  = (const float*)d_in[3];
    const float* WL1 = (const float*)d_in[4];
    const float* bL1 = (const float*)d_in[5];
    const float* WL2 = (const float*)d_in[6];
    const float* bL2 = (const float*)d_in[7];
    const int*   ir  = (const int*)d_in[8];
    const int*   ic  = (const int*)d_in[9];
    const float* iv  = (const float*)d_in[10];
    const int*   sr  = (const int*)d_in[11];
    const int*   sc  = (const int*)d_in[12];
    const float* sv  = (const float*)d_in[13];
    float* out = (float*)d_out;

    void *pf16, *ps16, *pcsr, *pP, *pbs;
    cudaGetSymbolAddress(&pf16, g_fused16);
    cudaGetSymbolAddress(&ps16, g_soc16);
    cudaGetSymbolAddress(&pcsr, g_csr);
    cudaGetSymbolAddress(&pP, g_P);
    cudaGetSymbolAddress(&pbs, g_bsum);

    __half* fused16[5];
    for (int k = 0; k <= 4; k++) fused16[k] = (__half*)pf16 + (size_t)k * NNF;
    __half* soc16[4];   // soc16[1..3]
    for (int l = 1; l <= 3; l++) soc16[l] = (__half*)ps16 + (size_t)(l - 1) * NUF;
    __half* socsrc[4];
    socsrc[0] = fused16[0];   // layer-0 soc source = fused16[0] user rows
    for (int l = 1; l < 4; l++) socsrc[l] = soc16[l];
    uint2* csr = (uint2*)pcsr;
    int* P = (int*)pP;
    int* bsum = (int*)pbs;

    // --- CSR build + fused16[0] ---
    zerobins_kernel<<<cdiv_ll(NBINS, 256), 256>>>(P);
    hist_kernel<<<H_I + H_S + H_B, 256>>>(
        P, ir, sr, (const float4*)uE, (const float4*)iE, (uint2*)fused16[0]);
    scan_blocks_kernel<<<SCAN_BLOCKS, 256>>>(P, bsum);
    addoff_kernel<<<cdiv_ll(NBINS, 256), 256>>>(P, bsum);
    scatter_kernel<<<H_I + H_S, 256>>>(P, csr, ir, ic, iv, sr, sc, sv);

    // --- fused SpMM + gate layers ---
    const int SPMM_BLOCKS = cdiv_ll((long long)N_NODE * 16, 256);  // 18750
    for (int k = 0; k < N_LAYER; k++) {
        spmm_gate_kernel<<<SPMM_BLOCKS, 256>>>(
            csr, P,
            fused16[k], socsrc[k],
            fused16[k + 1],
            (k < 3) ? soc16[k + 1] : (__half*)nullptr,
            Wg + (size_t)(k + 1) * 256, bg + (size_t)(k + 1) * 2);
    }

    final_kernel<<<cdiv_ll((long long)N_NODE * 32, 256), 256>>>(
        fused16[0], fused16[1], fused16[2], fused16[3], fused16[4],
        WL1, bL1, WL2, bL2, out);
}

// round 16
// speedup vs baseline: 1.1997x; 1.0125x over previous
#include <cuda_runtime.h>
#include <cuda_fp16.h>
#include <cstdint>

#define N_USER 100000
#define N_ITEM 200000
#define N_NODE 300000
#define LATDIM 64
#define E_INTER 4000000
#define E_SOC   2000000
#define E_TOT   (E_INTER + E_SOC)
#define N_LAYER 4
#define NBINS   (N_NODE + N_USER)   // inter bins [0,300000), soc bins [300000,400000)

#define NUF ((size_t)N_USER * LATDIM)
#define NNF ((size_t)N_NODE * LATDIM)

// fp16 embeddings: fused16[0]=fp16(concat(uE,iE)); fused16[1..3] gated outputs
// (fused16[4] never materialized — the final combine runs in the 4th SpMM's
// epilogue with f32-exact layer-4 vectors). soc16[1..3] raw soc accumulations.
__device__ __half g_fused16[4][NNF];
__device__ __half g_soc16[3][NUF];
// CSR: edges sorted by destination bin. rec = {col, val_f32_bits}.
__device__ uint2 g_csr[E_TOT];
__device__ int   g_P[NBINS];        // counts -> exclusive prefix -> bin ends
__device__ int   g_bsum[256];

// ---------------------------------------------------------------------------
// Stage 1: zero bin counters.
// ---------------------------------------------------------------------------
__global__ __launch_bounds__(256) void zerobins_kernel(int* __restrict__ P) {
    int i = blockIdx.x * 256 + threadIdx.x;
    if (i < NBINS) P[i] = 0;
}

// ---------------------------------------------------------------------------
// Stage 2: histogram of destination bins (+ build fused16[0], independent).
// ---------------------------------------------------------------------------
#define H_I 15625            // E_INTER / 256
#define H_S 7813             // ceil(E_SOC / 256)
#define H_B 1024             // fused16[0] build

__global__ __launch_bounds__(256) void hist_kernel(
    int* __restrict__ P,
    const int* __restrict__ ir, const int* __restrict__ sr,
    const float4* __restrict__ uE4, const float4* __restrict__ iE4,
    uint2* __restrict__ h0)
{
    unsigned b = blockIdx.x;
    int tid = threadIdx.x;
    if (b < H_I) {
        int e = (int)b * 256 + tid;
        atomicAdd(P + __ldg(ir + e), 1);
    } else if (b < H_I + H_S) {
        int e = (int)(b - H_I) * 256 + tid;
        if (e < E_SOC) atomicAdd(P + N_NODE + __ldg(sr + e), 1);
    } else {
        const size_t nU4 = NUF / 4, nN4 = NNF / 4;
        size_t stride = (size_t)H_B * 256;
        for (size_t i = (size_t)(b - H_I - H_S) * 256 + tid; i < nN4; i += stride) {
            float4 v = (i < nU4) ? __ldg(uE4 + i) : __ldg(iE4 + (i - nU4));
            __half2 a = __floats2half2_rn(v.x, v.y);
            __half2 c = __floats2half2_rn(v.z, v.w);
            uint2 st;
            st.x = *reinterpret_cast<unsigned*>(&a);
            st.y = *reinterpret_cast<unsigned*>(&c);
            h0[i] = st;
        }
    }
}

// ---------------------------------------------------------------------------
// Stage 3: per-block scan. Stage 4: addoff (re-derives the 196-entry top
// scan in shared per block).
// ---------------------------------------------------------------------------
#define SCAN_ELEMS 2048
#define SCAN_BLOCKS ((NBINS + SCAN_ELEMS - 1) / SCAN_ELEMS)   // 196

__global__ __launch_bounds__(256) void scan_blocks_kernel(
    int* __restrict__ P, int* __restrict__ bsum)
{
    __shared__ int sh[256];
    int b = blockIdx.x, t = threadIdx.x;
    int base = b * SCAN_ELEMS + t * 8;
    int v[8], s = 0;
    #pragma unroll
    for (int i = 0; i < 8; i++) {
        v[i] = (base + i < NBINS) ? P[base + i] : 0;
        s += v[i];
    }
    sh[t] = s;
    __syncthreads();
    #pragma unroll
    for (int off = 1; off < 256; off <<= 1) {
        int x = sh[t];
        int y = (t >= off) ? sh[t - off] : 0;
        __syncthreads();
        sh[t] = x + y;
        __syncthreads();
    }
    int run = sh[t] - s;
    #pragma unroll
    for (int i = 0; i < 8; i++) {
        int nv = run;
        run += v[i];
        if (base + i < NBINS) P[base + i] = nv;
    }
    if (t == 255) bsum[b] = run;
}

__global__ __launch_bounds__(256) void addoff_kernel(
    int* __restrict__ P, const int* __restrict__ bsum)
{
    __shared__ int sh[256];
    int t = threadIdx.x;
    int v = (t < SCAN_BLOCKS) ? __ldg(bsum + t) : 0;
    sh[t] = v;
    __syncthreads();
    #pragma unroll
    for (int off = 1; off < 256; off <<= 1) {
        int x = sh[t];
        int y = (t >= off) ? sh[t - off] : 0;
        __syncthreads();
        sh[t] = x + y;
        __syncthreads();
    }
    sh[t] = sh[t] - v;   // exclusive
    __syncthreads();
    int i = blockIdx.x * 256 + t;
    if (i < NBINS) P[i] += sh[i / SCAN_ELEMS];
}

// ---------------------------------------------------------------------------
// Stage 5: scatter edges into CSR slots (fetch-add turns P into bin ends).
// ---------------------------------------------------------------------------
__global__ __launch_bounds__(256) void scatter_kernel(
    int* __restrict__ P, uint2* __restrict__ csr,
    const int* __restrict__ ir, const int* __restrict__ ic, const float* __restrict__ iv,
    const int* __restrict__ sr, const int* __restrict__ sc, const float* __restrict__ sv)
{
    unsigned b = blockIdx.x;
    int tid = threadIdx.x;
    uint2 rec;
    int bin;
    if (b < H_I) {
        int e = (int)b * 256 + tid;
        bin = __ldg(ir + e);
        rec.x = (unsigned)__ldg(ic + e);
        rec.y = __float_as_uint(__ldg(iv + e));
    } else {
        int e = (int)(b - H_I) * 256 + tid;
        if (e >= E_SOC) return;
        bin = N_NODE + __ldg(sr + e);
        rec.x = (unsigned)__ldg(sc + e);
        rec.y = __float_as_uint(__ldg(sv + e));
    }
    int slot = atomicAdd(P + bin, 1);
    csr[slot] = rec;
}

// ---------------------------------------------------------------------------
// Convergent row accumulation: 16-lane group, lane owns 4 halves (uint2);
// gather = 128 B/edge = 1 L1 wavefront; f32 register accumulation. The batch
// count nbMax is warp-uniform (max over both halves) so the whole warp shares
// one instruction stream; padded slots have v=0 AND predicated-off gathers
// (h=0) — no memory work, exact zero contribution.
// ---------------------------------------------------------------------------
__device__ __forceinline__ void proc4p(
    uint2 rec, int j, int cnt, unsigned mask,
    const __half* __restrict__ X, int lane, float4& acc)
{
    int c0 = __shfl_sync(mask, (int)rec.x, j, 16);
    int c1 = __shfl_sync(mask, (int)rec.x, j + 1, 16);
    int c2 = __shfl_sync(mask, (int)rec.x, j + 2, 16);
    int c3 = __shfl_sync(mask, (int)rec.x, j + 3, 16);
    float v0 = __uint_as_float(__shfl_sync(mask, rec.y, j, 16));
    float v1 = __uint_as_float(__shfl_sync(mask, rec.y, j + 1, 16));
    float v2 = __uint_as_float(__shfl_sync(mask, rec.y, j + 2, 16));
    float v3 = __uint_as_float(__shfl_sync(mask, rec.y, j + 3, 16));
    uint2 h0 = make_uint2(0u, 0u), h1 = h0, h2 = h0, h3 = h0;
    if (j     < cnt) h0 = __ldg(reinterpret_cast<const uint2*>(X + (size_t)c0 * LATDIM) + lane);
    if (j + 1 < cnt) h1 = __ldg(reinterpret_cast<const uint2*>(X + (size_t)c1 * LATDIM) + lane);
    if (j + 2 < cnt) h2 = __ldg(reinterpret_cast<const uint2*>(X + (size_t)c2 * LATDIM) + lane);
    if (j + 3 < cnt) h3 = __ldg(reinterpret_cast<const uint2*>(X + (size_t)c3 * LATDIM) + lane);
    float2 a0 = __half22float2(*reinterpret_cast<__half2*>(&h0.x));
    float2 b0 = __half22float2(*reinterpret_cast<__half2*>(&h0.y));
    float2 a1 = __half22float2(*reinterpret_cast<__half2*>(&h1.x));
    float2 b1 = __half22float2(*reinterpret_cast<__half2*>(&h1.y));
    float2 a2 = __half22float2(*reinterpret_cast<__half2*>(&h2.x));
    float2 b2 = __half22float2(*reinterpret_cast<__half2*>(&h2.y));
    float2 a3 = __half22float2(*reinterpret_cast<__half2*>(&h3.x));
    float2 b3 = __half22float2(*reinterpret_cast<__half2*>(&h3.y));
    acc.x = fmaf(v0, a0.x, acc.x); acc.y = fmaf(v0, a0.y, acc.y);
    acc.z = fmaf(v0, b0.x, acc.z); acc.w = fmaf(v0, b0.y, acc.w);
    acc.x = fmaf(v1, a1.x, acc.x); acc.y = fmaf(v1, a1.y, acc.y);
    acc.z = fmaf(v1, b1.x, acc.z); acc.w = fmaf(v1, b1.y, acc.w);
    acc.x = fmaf(v2, a2.x, acc.x); acc.y = fmaf(v2, a2.y, acc.y);
    acc.z = fmaf(v2, b2.x, acc.z); acc.w = fmaf(v2, b2.y, acc.w);
    acc.x = fmaf(v3, a3.x, acc.x); acc.y = fmaf(v3, a3.y, acc.y);
    acc.z = fmaf(v3, b3.x, acc.z); acc.w = fmaf(v3, b3.y, acc.w);
}

__device__ __forceinline__ float4 row_accum_conv(
    const uint2* __restrict__ csr, int s, int e, int nbMax,
    const __half* __restrict__ X, int lane, unsigned mask)
{
    float4 acc = make_float4(0.f, 0.f, 0.f, 0.f);
    for (int b = 0; b < nbMax; b++) {
        int base = s + b * 16;
        int cnt = e - base;   // may be <= 0 for the shorter warp-half
        uint2 rec = (lane < cnt) ? __ldcs(csr + base + lane) : make_uint2(0u, 0u);
        #pragma unroll
        for (int j = 0; j < 16; j += 4)
            proc4p(rec, j, cnt, mask, X, lane, acc);
    }
    return acc;
}

__device__ __forceinline__ void store_h4(__half* O, size_t row, int lane, float4 v) {
    __half2 lo = __floats2half2_rn(v.x, v.y);
    __half2 hi = __floats2half2_rn(v.z, v.w);
    uint2 st;
    st.x = *reinterpret_cast<unsigned*>(&lo);
    st.y = *reinterpret_cast<unsigned*>(&hi);
    *(reinterpret_cast<uint2*>(O + row * LATDIM) + lane) = st;
}

__device__ __forceinline__ float4 load_f4(const __half* F, size_t row, int lane) {
    uint2 h = __ldg(reinterpret_cast<const uint2*>(F + row * LATDIM) + lane);
    float2 a = __half22float2(*reinterpret_cast<__half2*>(&h.x));
    float2 b = __half22float2(*reinterpret_cast<__half2*>(&h.y));
    return make_float4(a.x, a.y, b.x, b.y);
}

// Gate for user rows: returns gated combination of accS/accI (16-lane reduce).
__device__ __forceinline__ float4 apply_gate(
    float4 accS, float4 accI, const float* __restrict__ Wg,
    const float* __restrict__ bg, int lane, unsigned mask)
{
    int d = lane * 4;
    float a0 = accS.x * __ldg(Wg + d)        + accS.y * __ldg(Wg + d + 1)
             + accS.z * __ldg(Wg + d + 2)    + accS.w * __ldg(Wg + d + 3)
             + accI.x * __ldg(Wg + 64 + d)   + accI.y * __ldg(Wg + 64 + d + 1)
             + accI.z * __ldg(Wg + 64 + d + 2) + accI.w * __ldg(Wg + 64 + d + 3);
    float a1 = accS.x * __ldg(Wg + 128 + d)  + accS.y * __ldg(Wg + 128 + d + 1)
             + accS.z * __ldg(Wg + 128 + d + 2) + accS.w * __ldg(Wg + 128 + d + 3)
             + accI.x * __ldg(Wg + 192 + d)  + accI.y * __ldg(Wg + 192 + d + 1)
             + accI.z * __ldg(Wg + 192 + d + 2) + accI.w * __ldg(Wg + 192 + d + 3);
    #pragma unroll
    for (int o = 8; o; o >>= 1) {
        a0 += __shfl_xor_sync(mask, a0, o, 16);
        a1 += __shfl_xor_sync(mask, a1, o, 16);
    }
    a0 += __ldg(bg);
    a1 += __ldg(bg + 1);
    a0 = a0 > 0.f ? a0 : 0.01f * a0;
    a1 = a1 > 0.f ? a1 : 0.01f * a1;
    float mx = fmaxf(a0, a1);
    float e0 = __expf(a0 - mx), e1 = __expf(a1 - mx);
    float inv = 1.f / (e0 + e1);
    float m0 = e0 * inv, m1 = e1 * inv;
    float4 g;
    g.x = accS.x * m0 + accI.x * m1;
    g.y = accS.y * m0 + accI.y * m1;
    g.z = accS.z * m0 + accI.z * m1;
    g.w = accS.w * m0 + accI.w * m1;
    return g;
}

// ---------------------------------------------------------------------------
// Fused SpMM + gate (layers 1..3): 16-lane group per node row, convergent
// batch loops (nbMax = max over warp halves — grid is exact, no early exits,
// full-mask shfl is safe).
// ---------------------------------------------------------------------------
__global__ __launch_bounds__(256) void spmm_gate_kernel(
    const uint2* __restrict__ csr, const int* __restrict__ P,
    const __half* __restrict__ xI,   // fused16[k]
    const __half* __restrict__ xS,   // soc source layer k (user rows)
    __half* __restrict__ oF,         // fused16[k+1]
    __half* __restrict__ oS,         // soc16[k+1]
    const float* __restrict__ Wg, const float* __restrict__ bg)
{
    int t = blockIdx.x * 256 + threadIdx.x;
    int row = t >> 4;
    int lane = t & 15;
    unsigned mask = 0xFFFFu << (threadIdx.x & 16);
    bool isU = (row < N_USER);

    int sA = (row == 0) ? 0 : __ldg(P + row - 1);
    int eA = __ldg(P + row);
    int nbA = (eA - sA + 15) >> 4;
    int sB = 0, eB = 0, nbB = 0;
    if (isU) {
        sB = __ldg(P + N_NODE + row - 1);
        eB = __ldg(P + N_NODE + row);
        nbB = (eB - sB + 15) >> 4;
    }
    int nbAm = max(nbA, __shfl_xor_sync(0xffffffffu, nbA, 16));
    int nbBm = max(nbB, __shfl_xor_sync(0xffffffffu, nbB, 16));

    if (isU) {
        float4 accI = row_accum_conv(csr, sA, eA, nbAm, xI, lane, mask);
        float4 accS = row_accum_conv(csr, sB, eB, nbBm, xS, lane, mask);
        float4 g = apply_gate(accS, accI, Wg, bg, lane, mask);
        store_h4(oF, (size_t)row, lane, g);
        store_h4(oS, (size_t)row, lane, accS);
    } else {
        float4 acc = row_accum_conv(csr, sA, eA, nbAm, xI, lane, mask);
        store_h4(oF, (size_t)row, lane, acc);
    }
}

// ---------------------------------------------------------------------------
// Layer 4 + final combine fused: accumulate layer-4 vector (gated for users)
// in registers, then run the 5-layer attention combine and write f32 output.
// fused16[4] is never materialized; f[4] is f32-exact.
// ---------------------------------------------------------------------------
__global__ __launch_bounds__(256) void spmm_final_kernel(
    const uint2* __restrict__ csr, const int* __restrict__ P,
    const __half* __restrict__ xI,   // fused16[3]
    const __half* __restrict__ xS,   // soc16[3]
    const __half* __restrict__ F0, const __half* __restrict__ F1,
    const __half* __restrict__ F2, const __half* __restrict__ F3,
    const float* __restrict__ Wg, const float* __restrict__ bg,   // gate 4
    const float* __restrict__ WL1, const float* __restrict__ bL1,
    const float* __restrict__ WL2, const float* __restrict__ bL2,
    float* __restrict__ out)
{
    int t = blockIdx.x * 256 + threadIdx.x;
    int row = t >> 4;
    int lane = t & 15;
    unsigned mask = 0xFFFFu << (threadIdx.x & 16);
    bool isU = (row < N_USER);

    int sA = (row == 0) ? 0 : __ldg(P + row - 1);
    int eA = __ldg(P + row);
    int nbA = (eA - sA + 15) >> 4;
    int sB = 0, eB = 0, nbB = 0;
    if (isU) {
        sB = __ldg(P + N_NODE + row - 1);
        eB = __ldg(P + N_NODE + row);
        nbB = (eB - sB + 15) >> 4;
    }
    int nbAm = max(nbA, __shfl_xor_sync(0xffffffffu, nbA, 16));
    int nbBm = max(nbB, __shfl_xor_sync(0xffffffffu, nbB, 16));

    float4 f4;
    if (isU) {
        float4 accI = row_accum_conv(csr, sA, eA, nbAm, xI, lane, mask);
        float4 accS = row_accum_conv(csr, sB, eB, nbBm, xS, lane, mask);
        f4 = apply_gate(accS, accI, Wg, bg, lane, mask);
    } else {
        f4 = row_accum_conv(csr, sA, eA, nbAm, xI, lane, mask);
    }

    // final combine
    const float* W = isU ? WL1 : WL2;
    const float* bias = isU ? bL1 : bL2;
    float4 f[5];
    f[0] = load_f4(F0, (size_t)row, lane);
    f[1] = load_f4(F1, (size_t)row, lane);
    f[2] = load_f4(F2, (size_t)row, lane);
    f[3] = load_f4(F3, (size_t)row, lane);
    f[4] = f4;

    float lg[5];
    #pragma unroll
    for (int j = 0; j < 5; j++) {
        float p = 0.f;
        #pragma unroll
        for (int k = 0; k < 5; k++) {
            float4 wv = __ldg(reinterpret_cast<const float4*>(W + j * 320 + k * 64) + lane);
            p = fmaf(f[k].x, wv.x, p);
            p = fmaf(f[k].y, wv.y, p);
            p = fmaf(f[k].z, wv.z, p);
            p = fmaf(f[k].w, wv.w, p);
        }
        lg[j] = p;
    }
    #pragma unroll
    for (int o = 8; o; o >>= 1) {
        #pragma unroll
        for (int j = 0; j < 5; j++)
            lg[j] += __shfl_xor_sync(mask, lg[j], o, 16);
    }
    float mx = -1e30f;
    #pragma unroll
    for (int j = 0; j < 5; j++) {
        lg[j] += __ldg(bias + j);
        lg[j] = lg[j] > 0.f ? lg[j] : 0.01f * lg[j];
        mx = fmaxf(mx, lg[j]);
    }
    float s = 0.f;
    #pragma unroll
    for (int j = 0; j < 5; j++) { lg[j] = __expf(lg[j] - mx); s += lg[j]; }
    float inv = 1.f / s;
    float4 o4 = make_float4(0.f, 0.f, 0.f, 0.f);
    #pragma unroll
    for (int j = 0; j < 5; j++) {
        float wk = lg[j] * inv;
        o4.x = fmaf(wk, f[j].x, o4.x);
        o4.y = fmaf(wk, f[j].y, o4.y);
        o4.z = fmaf(wk, f[j].z, o4.z);
        o4.w = fmaf(wk, f[j].w, o4.w);
    }
    reinterpret_cast<float4*>(out)[(size_t)row * 16 + lane] = o4;
}

// ---------------------------------------------------------------------------
// host
// ---------------------------------------------------------------------------
static inline int cdiv_ll(long long a, int b) { return (int)((a + b - 1) / b); }

extern "C" void kernel_launch(void* const* d_in, const int* in_sizes, int n_in,
                              void* d_out, int out_size)
{
    const float* uE  = (const float*)d_in[0];
    const float* iE  = (const float*)d_in[1];
    const float* Wg  = (const float*)d_in[2];
    const float* bg  = (const float*)d_in[3];
    const float* WL1 = (const float*)d_in[4];
    const float* bL1 = (const float*)d_in[5];
    const float* WL2 = (const float*)d_in[6];
    const float* bL2 = (const float*)d_in[7];
    const int*   ir  = (const int*)d_in[8];
    const int*   ic  = (const int*)d_in[9];
    const float* iv  = (const float*)d_in[10];
    const int*   sr  = (const int*)d_in[11];
    const int*   sc  = (const int*)d_in[12];
    const float* sv  = (const float*)d_in[13];
    float* out = (float*)d_out;

    void *pf16, *ps16, *pcsr, *pP, *pbs;
    cudaGetSymbolAddress(&pf16, g_fused16);
    cudaGetSymbolAddress(&ps16, g_soc16);
    cudaGetSymbolAddress(&pcsr, g_csr);
    cudaGetSymbolAddress(&pP, g_P);
    cudaGetSymbolAddress(&pbs, g_bsum);

    __half* fused16[4];
    for (int k = 0; k < 4; k++) fused16[k] = (__half*)pf16 + (size_t)k * NNF;
    __half* soc16[4];   // soc16[1..3]
    for (int l = 1; l <= 3; l++) soc16[l] = (__half*)ps16 + (size_t)(l - 1) * NUF;
    __half* socsrc[4];
    socsrc[0] = fused16[0];   // layer-0 soc source = fused16[0] user rows
    for (int l = 1; l < 4; l++) socsrc[l] = soc16[l];
    uint2* csr = (uint2*)pcsr;
    int* P = (int*)pP;
    int* bsum = (int*)pbs;

    // --- CSR build + fused16[0] ---
    zerobins_kernel<<<cdiv_ll(NBINS, 256), 256>>>(P);
    hist_kernel<<<H_I + H_S + H_B, 256>>>(
        P, ir, sr, (const float4*)uE, (const float4*)iE, (uint2*)fused16[0]);
    scan_blocks_kernel<<<SCAN_BLOCKS, 256>>>(P, bsum);
    addoff_kernel<<<cdiv_ll(NBINS, 256), 256>>>(P, bsum);
    scatter_kernel<<<H_I + H_S, 256>>>(P, csr, ir, ic, iv, sr, sc, sv);

    // --- fused SpMM + gate layers 1..3 ---
    const int SPMM_BLOCKS = cdiv_ll((long long)N_NODE * 16, 256);  // 18750
    for (int k = 0; k < 3; k++) {
        spmm_gate_kernel<<<SPMM_BLOCKS, 256>>>(
            csr, P,
            fused16[k], socsrc[k],
            fused16[k + 1], soc16[k + 1],
            Wg + (size_t)(k + 1) * 256, bg + (size_t)(k + 1) * 2);
    }

    // --- layer 4 + final combine fused ---
    spmm_final_kernel<<<SPMM_BLOCKS, 256>>>(
        csr, P,
        fused16[3], socsrc[3],
        fused16[0], fused16[1], fused16[2], fused16[3],
        Wg + (size_t)4 * 256, bg + (size_t)4 * 2,
        WL1, bL1, WL2, bL2, out);
}